// round 16
// baseline (speedup 1.0000x reference)
#include <cuda_runtime.h>
#include <cuda_fp16.h>
#include <mma.h>
#include <cstdint>

using namespace nvcuda;

#define BB   32
#define TT   512
#define DD   256
#define FF   256
#define MEL  2304
#define EPSF 1e-5f

#define TPB    512      // 16 warps
#define NCHUNK 24       // K=768 in chunks of 32
#define MTILE  128
#define NTILES 4        // 128 blocks

// ---------------- device scratch ----------------
__device__ __align__(128) __half g_xpad [(size_t)BB*(TT+2)*DD];
__device__ __align__(128) __half g_h1   [(size_t)BB*(TT+2)*FF];
__device__ __align__(128) __half g_wB   [2*768*256];              // [stage][kcol][f]
__device__ int g_idx[BB*MEL];

// ---------------- conv smem layout (bytes) ----------------
#define STAGE_BYTES 27136
#define OFF_B    10240
#define OFF_PAR  135168
#define SMEM_BYTES 139264
#define A_STRIDE 40
#define B_STRIDE 264
#define C_STRIDE 264

__device__ __forceinline__ uint32_t smem_u32(const void* p) {
    uint32_t a;
    asm("{ .reg .u64 t; cvta.to.shared.u64 t, %1; cvt.u32.u64 %0, t; }" : "=r"(a) : "l"(p));
    return a;
}
__device__ __forceinline__ void cp16(uint32_t dst, const void* src) {
    asm volatile("cp.async.cg.shared.global [%0], [%1], 16;" :: "r"(dst), "l"(src));
}
__device__ __forceinline__ void cp_commit() { asm volatile("cp.async.commit_group;" ::: "memory"); }
template<int N> __device__ __forceinline__ void cp_wait() { asm volatile("cp.async.wait_group %0;" :: "n"(N) : "memory"); }

// ---------------- fused prep: cum_idx (32) | prep_w (16) | prep_x (516) ----------------
#define PW_PITCH 778
#define PREP_SMEM (32*PW_PITCH*2)
#define NXBLK 516
#define NTOTX (BB*(TT+2)*DD)

__global__ __launch_bounds__(512)
void prep_all(const float* __restrict__ x,
              const float* __restrict__ w1,
              const float* __restrict__ w2,
              const int*   __restrict__ target) {
    extern __shared__ char dsm[];
    const int j   = blockIdx.x;
    const int tid = threadIdx.x;
    const int wid = tid >> 5, lane = tid & 31;

    if (j < 32) {
        // cumsum + searchsorted for batch j
        int* cs   = (int*)dsm;
        int* wsum = (int*)dsm + 512;
        const int b = j, t = tid;
        int sc = target[b*TT + t];
        #pragma unroll
        for (int o = 1; o < 32; o <<= 1) {
            int n = __shfl_up_sync(0xffffffffu, sc, o);
            if (lane >= o) sc += n;
        }
        if (lane == 31) wsum[wid] = sc;
        __syncthreads();
        if (wid == 0 && lane < 16) {
            int w = wsum[lane];
            #pragma unroll
            for (int o = 1; o < 16; o <<= 1) {
                int n = __shfl_up_sync(0xffffu, w, o);
                if (lane >= o) w += n;
            }
            wsum[lane] = w;
        }
        __syncthreads();
        cs[t] = sc + (wid ? wsum[wid-1] : 0);
        __syncthreads();
        const int total = cs[TT-1];
        for (int to = t; to < MEL; to += TT) {
            int lo = 0, hi = TT;
            while (lo < hi) {
                int mid = (lo + hi) >> 1;
                if (cs[mid] <= to) lo = mid + 1; else hi = mid;
            }
            g_idx[b*MEL + to] = (to < total) ? min(lo, TT-1) : -1;
        }
    } else if (j < 48) {
        // weight transpose: 32 f-rows x 768 m-cols, coalesced both sides
        const int jj    = j - 32;
        const int stg   = jj >> 3;
        const int f0    = (jj & 7) * 32;
        const float* w  = stg ? w2 : w1;
        __half* S = (__half*)dsm;
        #pragma unroll
        for (int it = 0; it < 12; ++it) {
            int u  = tid + it*512;
            int r  = u / 192;
            int m  = (u % 192) * 4;
            float4 v = __ldg((const float4*)(w + (size_t)(f0 + r)*768 + m));
            __half* dst = S + r*PW_PITCH + m;
            dst[0] = __float2half(v.x);
            dst[1] = __float2half(v.y);
            dst[2] = __float2half(v.z);
            dst[3] = __float2half(v.w);
        }
        __syncthreads();
        for (int i = 0; i < 48; ++i) {
            int kcol = wid*48 + i;
            int k = kcol >> 8, d = kcol & 255;
            int m = d*3 + k;
            g_wB[((size_t)(stg*768 + kcol))*256 + f0 + lane] = S[lane*PW_PITCH + m];
        }
    } else {
        // x convert + h1 edge zero
        const int bb = j - 48;
        #pragma unroll
        for (int it = 0; it < 16; ++it) {
            int i = (bb*16 + it)*512 + tid;
            if (i < NTOTX) {
                int d   = i & (DD-1);
                int row = i >> 8;
                int t   = row % (TT+2);
                int b   = row / (TT+2);
                float v = (t == 0 || t == TT+1) ? 0.f : x[((size_t)(b*TT + t - 1))*DD + d];
                g_xpad[i] = __float2half(v);
            }
        }
        if (bb == 0) {
            #pragma unroll
            for (int it = 0; it < 32; ++it) {
                int i = it*512 + tid;
                int d = i & (FF-1);
                int r = i >> 8;
                int b = r >> 1;
                int t = (r & 1) ? (TT+1) : 0;
                g_h1[((size_t)(b*(TT+2) + t))*FF + d] = __float2half(0.f);
            }
        }
    }
}

// ---------------- conv: R11-exact (16 warps, 32x64 warp tiles, 96 regs) ----------------
template<int STAGE>
__global__ __launch_bounds__(576, 1)
void conv_wmma(const float* __restrict__ bias,
               const float* __restrict__ gamma,
               const float* __restrict__ beta,
               const float* __restrict__ lin_w,
               const float* __restrict__ lin_b,
               float* __restrict__ dur_out) {
    extern __shared__ char smem[];
    const uint32_t sbase = smem_u32(smem);
    const int tid  = threadIdx.x;
    const int wid  = tid >> 5;
    const int lane = tid & 31;
    const int b    = blockIdx.x >> 2;
    const int t0   = (blockIdx.x & 3) * MTILE;

    const __half* __restrict__ srcA = STAGE ? g_h1 : g_xpad;
    float* Cs  = (float*)smem;
    float* par = (float*)(smem + OFF_PAR);

    if (tid < 256) {
        par[tid]       = bias [tid];
        par[256 + tid] = gamma[tid];
        par[512 + tid] = beta [tid];
        par[768 + tid] = STAGE ? lin_w[tid] : 0.f;
    }

    auto load_chunk = [&](int c) {
        const uint32_t st = sbase + (uint32_t)(c % 3) * STAGE_BYTES;
        const int k   = c >> 3;
        const int d0  = (c & 7) * 32;
        {
            int r = tid >> 2, seg = tid & 3;
            size_t go = ((size_t)(b*(TT+2) + t0 + k + r))*DD + d0 + seg*8;
            cp16(st + r*(A_STRIDE*2) + seg*16, srcA + go);
        }
        {
            const size_t bbase = ((size_t)(STAGE*768 + c*32))*256;
            #pragma unroll
            for (int it = 0; it < 2; ++it) {
                int u = tid + it*TPB;
                int r = u >> 5, seg = u & 31;
                cp16(st + OFF_B + r*(B_STRIDE*2) + seg*16, g_wB + bbase + (size_t)r*256 + seg*8);
            }
        }
        cp_commit();
    };

    const int wm = wid & 3;
    const int wn = wid >> 2;

    wmma::fragment<wmma::accumulator, 16, 16, 16, float> acc[2][4];
    #pragma unroll
    for (int i = 0; i < 2; ++i)
        #pragma unroll
        for (int j = 0; j < 4; ++j)
            wmma::fill_fragment(acc[i][j], 0.f);

    load_chunk(0);
    load_chunk(1);

    for (int c = 0; c < NCHUNK; ++c) {
        if (c < NCHUNK - 1) cp_wait<1>(); else cp_wait<0>();
        __syncthreads();
        const char* stg = smem + (size_t)(c % 3) * STAGE_BYTES;
        const __half* As = (const __half*)(stg);
        const __half* Bs = (const __half*)(stg + OFF_B);
        #pragma unroll
        for (int ks = 0; ks < 2; ++ks) {
            wmma::fragment<wmma::matrix_a, 16, 16, 16, __half, wmma::row_major> af[2];
            #pragma unroll
            for (int i = 0; i < 2; ++i)
                wmma::load_matrix_sync(af[i], As + (wm*32 + i*16)*A_STRIDE + ks*16, A_STRIDE);
            #pragma unroll
            for (int j = 0; j < 4; ++j) {
                wmma::fragment<wmma::matrix_b, 16, 16, 16, __half, wmma::row_major> bf;
                wmma::load_matrix_sync(bf, Bs + (ks*16)*B_STRIDE + wn*64 + j*16, B_STRIDE);
                #pragma unroll
                for (int i = 0; i < 2; ++i)
                    wmma::mma_sync(acc[i][j], af[i], bf, acc[i][j]);
            }
        }
        if (c + 2 < NCHUNK) load_chunk(c + 2);
    }

    __syncthreads();
    #pragma unroll
    for (int i = 0; i < 2; ++i)
        #pragma unroll
        for (int j = 0; j < 4; ++j)
            wmma::store_matrix_sync(Cs + (size_t)(wm*32 + i*16)*C_STRIDE + wn*64 + j*16,
                                    acc[i][j], C_STRIDE, wmma::mem_row_major);
    __syncthreads();

    #pragma unroll
    for (int rr = 0; rr < 8; ++rr) {
        const int row = wid*8 + rr;
        float v[8];
        float s = 0.f, ss = 0.f;
        #pragma unroll
        for (int j = 0; j < 8; ++j) {
            v[j] = Cs[(size_t)row*C_STRIDE + lane + j*32] + par[lane + j*32];
            s  += v[j];
            ss += v[j]*v[j];
        }
        #pragma unroll
        for (int o = 16; o > 0; o >>= 1) {
            s  += __shfl_xor_sync(0xffffffffu, s,  o);
            ss += __shfl_xor_sync(0xffffffffu, ss, o);
        }
        const float mu = s * (1.f/FF);
        const float rs = rsqrtf(ss * (1.f/FF) - mu*mu + EPSF);

        if (!STAGE) {
            size_t ro = ((size_t)(b*(TT+2) + t0 + 1 + row))*FF;
            #pragma unroll
            for (int j = 0; j < 8; ++j) {
                int cch = lane + j*32;
                float w = fmaf((v[j] - mu)*rs, par[256 + cch], par[512 + cch]);
                g_h1[ro + cch] = __float2half(fmaxf(w, 0.f));
            }
        } else {
            float dot = 0.f;
            #pragma unroll
            for (int j = 0; j < 8; ++j) {
                int cch = lane + j*32;
                float w = fmaf((v[j] - mu)*rs, par[256 + cch], par[512 + cch]);
                dot = fmaf(fmaxf(w, 0.f), par[768 + cch], dot);
            }
            #pragma unroll
            for (int o = 16; o > 0; o >>= 1)
                dot += __shfl_xor_sync(0xffffffffu, dot, o);
            if (lane == 0)
                dur_out[b*TT + t0 + row] = fmaxf(dot + lin_b[0], 0.f);
        }
    }
}

// ---------------- gather half: rows [rowbase, rowbase + NROWS/2), 2 rows/thread ----------------
__device__ __forceinline__ void st_cs(float4* p, float4 v) {
    asm volatile("st.global.cs.v4.f32 [%0], {%1,%2,%3,%4};"
                 :: "l"(p), "f"(v.x), "f"(v.y), "f"(v.z), "f"(v.w) : "memory");
}
#define NROWS   (BB*MEL)          // 73728
#define HALF    (NROWS/2)         // 36864
#define QHALF   (HALF/2)          // 18432 thread-rows per half
__global__ __launch_bounds__(256)
void gather_half(const float* __restrict__ x, float* __restrict__ out, int rowbase) {
    const long long u  = (long long)blockIdx.x * blockDim.x + threadIdx.x;
    const long long NU = (long long)QHALF * 32;
    if (u >= NU) return;
    const int c8 = (int)(u & 31);
    const long long rowa = rowbase + (u >> 5);
    const long long rowb = rowa + QHALF;
    const int ba = (int)(rowa / MEL);
    const int bb = (int)(rowb / MEL);
    const int ia = __ldg(&g_idx[rowa]);
    const int ib = __ldg(&g_idx[rowb]);
    float4 a0 = make_float4(0.f,0.f,0.f,0.f), a1 = a0, b0 = a0, b1 = a0;
    if (ia >= 0) {
        const float4* s = reinterpret_cast<const float4*>(x) + ((long long)ba*TT + ia)*(DD/4) + c8*2;
        a0 = __ldg(s); a1 = __ldg(s + 1);
    }
    if (ib >= 0) {
        const float4* s = reinterpret_cast<const float4*>(x) + ((long long)bb*TT + ib)*(DD/4) + c8*2;
        b0 = __ldg(s); b1 = __ldg(s + 1);
    }
    float4* da = reinterpret_cast<float4*>(out) + rowa*(DD/4) + c8*2;
    float4* db = reinterpret_cast<float4*>(out) + rowb*(DD/4) + c8*2;
    st_cs(da, a0); st_cs(da + 1, a1);
    st_cs(db, b0); st_cs(db + 1, b1);
}

// ---------------- launch ----------------
extern "C" void kernel_launch(void* const* d_in, const int* in_sizes, int n_in,
                              void* d_out, int out_size) {
    int base = 2;
    if (n_in >= 13 && in_sizes[2] == 1) base = 3;

    const float* x      = (const float*)d_in[0];
    const int*   target = (const int*)  d_in[1];
    const float* c1w = (const float*)d_in[base + 0];
    const float* c1b = (const float*)d_in[base + 1];
    const float* l1g = (const float*)d_in[base + 2];
    const float* l1b = (const float*)d_in[base + 3];
    const float* c2w = (const float*)d_in[base + 4];
    const float* c2b = (const float*)d_in[base + 5];
    const float* l2g = (const float*)d_in[base + 6];
    const float* l2b = (const float*)d_in[base + 7];
    const float* lw  = (const float*)d_in[base + 8];
    const float* lb  = (const float*)d_in[base + 9];

    float* out = (float*)d_out;
    float* dur = out + (size_t)BB * MEL * DD;

    cudaFuncSetAttribute(conv_wmma<0>, cudaFuncAttributeMaxDynamicSharedMemorySize, SMEM_BYTES);
    cudaFuncSetAttribute(conv_wmma<1>, cudaFuncAttributeMaxDynamicSharedMemorySize, SMEM_BYTES);
    cudaFuncSetAttribute(prep_all,     cudaFuncAttributeMaxDynamicSharedMemorySize, PREP_SMEM);

    const long long NU = (long long)QHALF * 32;
    const int gatherBlocks = (int)((NU + 255)/256);

    cudaStream_t s2 = nullptr;
    cudaEvent_t eP = nullptr, eC1 = nullptr, eJ = nullptr;
    bool forked = (cudaStreamCreateWithFlags(&s2, cudaStreamNonBlocking) == cudaSuccess)
               && (cudaEventCreateWithFlags(&eP,  cudaEventDisableTiming) == cudaSuccess)
               && (cudaEventCreateWithFlags(&eC1, cudaEventDisableTiming) == cudaSuccess)
               && (cudaEventCreateWithFlags(&eJ,  cudaEventDisableTiming) == cudaSuccess);

    if (forked) {
        // shared prefix on default stream (w + x + cum)
        prep_all<<<48 + NXBLK, 512, PREP_SMEM>>>(x, c1w, c2w, target);
        cudaEventRecord(eP, 0);

        // chain B, part 1: half the gather hides under the conv window
        cudaStreamWaitEvent(s2, eP, 0);
        gather_half<<<gatherBlocks, 256, 0, s2>>>(x, out, 0);

        // chain A: both convs
        conv_wmma<0><<<BB*NTILES, TPB, SMEM_BYTES>>>(c1b, l1g, l1b, lw, lb, nullptr);
        conv_wmma<1><<<BB*NTILES, TPB, SMEM_BYTES>>>(c2b, l2g, l2b, lw, lb, dur);
        cudaEventRecord(eC1, 0);

        // chain B, part 2: runs at full width after the convs drain
        cudaStreamWaitEvent(s2, eC1, 0);
        gather_half<<<gatherBlocks, 256, 0, s2>>>(x, out, HALF);
        cudaEventRecord(eJ, s2);

        cudaStreamWaitEvent(0, eJ, 0);

        cudaEventDestroy(eP);
        cudaEventDestroy(eC1);
        cudaEventDestroy(eJ);
        cudaStreamDestroy(s2);
    } else {
        if (s2)  cudaStreamDestroy(s2);
        if (eP)  cudaEventDestroy(eP);
        if (eC1) cudaEventDestroy(eC1);
        if (eJ)  cudaEventDestroy(eJ);

        prep_all<<<48 + NXBLK, 512, PREP_SMEM>>>(x, c1w, c2w, target);
        gather_half<<<gatherBlocks, 256>>>(x, out, 0);
        gather_half<<<gatherBlocks, 256>>>(x, out, HALF);
        conv_wmma<0><<<BB*NTILES, TPB, SMEM_BYTES>>>(c1b, l1g, l1b, lw, lb, nullptr);
        conv_wmma<1><<<BB*NTILES, TPB, SMEM_BYTES>>>(c2b, l2g, l2b, lw, lb, dur);
    }
}

// round 17
// speedup vs baseline: 1.6636x; 1.6636x over previous
#include <cuda_runtime.h>
#include <cuda_fp16.h>
#include <mma.h>
#include <cstdint>

using namespace nvcuda;

#define BB   32
#define TT   512
#define DD   256
#define FF   256
#define MEL  2304
#define EPSF 1e-5f

#define TPB    512      // 16 warps
#define NCHUNK 24       // K=768 in chunks of 32
#define MTILE  128
#define NTILES 4        // 128 blocks

// ---------------- device scratch ----------------
__device__ __align__(128) __half g_xpad [(size_t)BB*(TT+2)*DD];
__device__ __align__(128) __half g_h1   [(size_t)BB*(TT+2)*FF];
__device__ __align__(128) __half g_wB   [2*768*256];              // [stage][kcol][f]
__device__ int g_idx[BB*MEL];

// ---------------- conv smem layout (bytes) ----------------
#define STAGE_BYTES 27136
#define OFF_B    10240
#define OFF_PAR  135168
#define SMEM_BYTES 139264
#define A_STRIDE 40
#define B_STRIDE 264
#define C_STRIDE 264

__device__ __forceinline__ uint32_t smem_u32(const void* p) {
    uint32_t a;
    asm("{ .reg .u64 t; cvta.to.shared.u64 t, %1; cvt.u32.u64 %0, t; }" : "=r"(a) : "l"(p));
    return a;
}
__device__ __forceinline__ void cp16(uint32_t dst, const void* src) {
    asm volatile("cp.async.cg.shared.global [%0], [%1], 16;" :: "r"(dst), "l"(src));
}
__device__ __forceinline__ void cp_commit() { asm volatile("cp.async.commit_group;" ::: "memory"); }
template<int N> __device__ __forceinline__ void cp_wait() { asm volatile("cp.async.wait_group %0;" :: "n"(N) : "memory"); }

// ---------------- fused prep: cum_idx (32) | prep_w (16) | prep_x (516) ----------------
#define PW_PITCH 778
#define PREP_SMEM (32*PW_PITCH*2)
#define NXBLK 516
#define NTOTX (BB*(TT+2)*DD)

__global__ __launch_bounds__(512)
void prep_all(const float* __restrict__ x,
              const float* __restrict__ w1,
              const float* __restrict__ w2,
              const int*   __restrict__ target) {
    extern __shared__ char dsm[];
    const int j   = blockIdx.x;
    const int tid = threadIdx.x;
    const int wid = tid >> 5, lane = tid & 31;

    if (j < 32) {
        int* cs   = (int*)dsm;
        int* wsum = (int*)dsm + 512;
        const int b = j, t = tid;
        int sc = target[b*TT + t];
        #pragma unroll
        for (int o = 1; o < 32; o <<= 1) {
            int n = __shfl_up_sync(0xffffffffu, sc, o);
            if (lane >= o) sc += n;
        }
        if (lane == 31) wsum[wid] = sc;
        __syncthreads();
        if (wid == 0 && lane < 16) {
            int w = wsum[lane];
            #pragma unroll
            for (int o = 1; o < 16; o <<= 1) {
                int n = __shfl_up_sync(0xffffu, w, o);
                if (lane >= o) w += n;
            }
            wsum[lane] = w;
        }
        __syncthreads();
        cs[t] = sc + (wid ? wsum[wid-1] : 0);
        __syncthreads();
        const int total = cs[TT-1];
        for (int to = t; to < MEL; to += TT) {
            int lo = 0, hi = TT;
            while (lo < hi) {
                int mid = (lo + hi) >> 1;
                if (cs[mid] <= to) lo = mid + 1; else hi = mid;
            }
            g_idx[b*MEL + to] = (to < total) ? min(lo, TT-1) : -1;
        }
    } else if (j < 48) {
        const int jj    = j - 32;
        const int stg   = jj >> 3;
        const int f0    = (jj & 7) * 32;
        const float* w  = stg ? w2 : w1;
        __half* S = (__half*)dsm;
        #pragma unroll
        for (int it = 0; it < 12; ++it) {
            int u  = tid + it*512;
            int r  = u / 192;
            int m  = (u % 192) * 4;
            float4 v = __ldg((const float4*)(w + (size_t)(f0 + r)*768 + m));
            __half* dst = S + r*PW_PITCH + m;
            dst[0] = __float2half(v.x);
            dst[1] = __float2half(v.y);
            dst[2] = __float2half(v.z);
            dst[3] = __float2half(v.w);
        }
        __syncthreads();
        for (int i = 0; i < 48; ++i) {
            int kcol = wid*48 + i;
            int k = kcol >> 8, d = kcol & 255;
            int m = d*3 + k;
            g_wB[((size_t)(stg*768 + kcol))*256 + f0 + lane] = S[lane*PW_PITCH + m];
        }
    } else {
        const int bb = j - 48;
        #pragma unroll
        for (int it = 0; it < 16; ++it) {
            int i = (bb*16 + it)*512 + tid;
            if (i < NTOTX) {
                int d   = i & (DD-1);
                int row = i >> 8;
                int t   = row % (TT+2);
                int b   = row / (TT+2);
                float v = (t == 0 || t == TT+1) ? 0.f : x[((size_t)(b*TT + t - 1))*DD + d];
                g_xpad[i] = __float2half(v);
            }
        }
        if (bb == 0) {
            #pragma unroll
            for (int it = 0; it < 32; ++it) {
                int i = it*512 + tid;
                int d = i & (FF-1);
                int r = i >> 8;
                int b = r >> 1;
                int t = (r & 1) ? (TT+1) : 0;
                g_h1[((size_t)(b*(TT+2) + t))*FF + d] = __float2half(0.f);
            }
        }
    }
}

// ---------------- conv: R11-exact ----------------
template<int STAGE>
__global__ __launch_bounds__(576, 1)
void conv_wmma(const float* __restrict__ bias,
               const float* __restrict__ gamma,
               const float* __restrict__ beta,
               const float* __restrict__ lin_w,
               const float* __restrict__ lin_b,
               float* __restrict__ dur_out) {
    extern __shared__ char smem[];
    const uint32_t sbase = smem_u32(smem);
    const int tid  = threadIdx.x;
    const int wid  = tid >> 5;
    const int lane = tid & 31;
    const int b    = blockIdx.x >> 2;
    const int t0   = (blockIdx.x & 3) * MTILE;

    const __half* __restrict__ srcA = STAGE ? g_h1 : g_xpad;
    float* Cs  = (float*)smem;
    float* par = (float*)(smem + OFF_PAR);

    if (tid < 256) {
        par[tid]       = bias [tid];
        par[256 + tid] = gamma[tid];
        par[512 + tid] = beta [tid];
        par[768 + tid] = STAGE ? lin_w[tid] : 0.f;
    }

    auto load_chunk = [&](int c) {
        const uint32_t st = sbase + (uint32_t)(c % 3) * STAGE_BYTES;
        const int k   = c >> 3;
        const int d0  = (c & 7) * 32;
        {
            int r = tid >> 2, seg = tid & 3;
            size_t go = ((size_t)(b*(TT+2) + t0 + k + r))*DD + d0 + seg*8;
            cp16(st + r*(A_STRIDE*2) + seg*16, srcA + go);
        }
        {
            const size_t bbase = ((size_t)(STAGE*768 + c*32))*256;
            #pragma unroll
            for (int it = 0; it < 2; ++it) {
                int u = tid + it*TPB;
                int r = u >> 5, seg = u & 31;
                cp16(st + OFF_B + r*(B_STRIDE*2) + seg*16, g_wB + bbase + (size_t)r*256 + seg*8);
            }
        }
        cp_commit();
    };

    const int wm = wid & 3;
    const int wn = wid >> 2;

    wmma::fragment<wmma::accumulator, 16, 16, 16, float> acc[2][4];
    #pragma unroll
    for (int i = 0; i < 2; ++i)
        #pragma unroll
        for (int j = 0; j < 4; ++j)
            wmma::fill_fragment(acc[i][j], 0.f);

    load_chunk(0);
    load_chunk(1);

    for (int c = 0; c < NCHUNK; ++c) {
        if (c < NCHUNK - 1) cp_wait<1>(); else cp_wait<0>();
        __syncthreads();
        const char* stg = smem + (size_t)(c % 3) * STAGE_BYTES;
        const __half* As = (const __half*)(stg);
        const __half* Bs = (const __half*)(stg + OFF_B);
        #pragma unroll
        for (int ks = 0; ks < 2; ++ks) {
            wmma::fragment<wmma::matrix_a, 16, 16, 16, __half, wmma::row_major> af[2];
            #pragma unroll
            for (int i = 0; i < 2; ++i)
                wmma::load_matrix_sync(af[i], As + (wm*32 + i*16)*A_STRIDE + ks*16, A_STRIDE);
            #pragma unroll
            for (int j = 0; j < 4; ++j) {
                wmma::fragment<wmma::matrix_b, 16, 16, 16, __half, wmma::row_major> bf;
                wmma::load_matrix_sync(bf, Bs + (ks*16)*B_STRIDE + wn*64 + j*16, B_STRIDE);
                #pragma unroll
                for (int i = 0; i < 2; ++i)
                    wmma::mma_sync(acc[i][j], af[i], bf, acc[i][j]);
            }
        }
        if (c + 2 < NCHUNK) load_chunk(c + 2);
    }

    __syncthreads();
    #pragma unroll
    for (int i = 0; i < 2; ++i)
        #pragma unroll
        for (int j = 0; j < 4; ++j)
            wmma::store_matrix_sync(Cs + (size_t)(wm*32 + i*16)*C_STRIDE + wn*64 + j*16,
                                    acc[i][j], C_STRIDE, wmma::mem_row_major);
    __syncthreads();

    #pragma unroll
    for (int rr = 0; rr < 8; ++rr) {
        const int row = wid*8 + rr;
        float v[8];
        float s = 0.f, ss = 0.f;
        #pragma unroll
        for (int j = 0; j < 8; ++j) {
            v[j] = Cs[(size_t)row*C_STRIDE + lane + j*32] + par[lane + j*32];
            s  += v[j];
            ss += v[j]*v[j];
        }
        #pragma unroll
        for (int o = 16; o > 0; o >>= 1) {
            s  += __shfl_xor_sync(0xffffffffu, s,  o);
            ss += __shfl_xor_sync(0xffffffffu, ss, o);
        }
        const float mu = s * (1.f/FF);
        const float rs = rsqrtf(ss * (1.f/FF) - mu*mu + EPSF);

        if (!STAGE) {
            size_t ro = ((size_t)(b*(TT+2) + t0 + 1 + row))*FF;
            #pragma unroll
            for (int j = 0; j < 8; ++j) {
                int cch = lane + j*32;
                float w = fmaf((v[j] - mu)*rs, par[256 + cch], par[512 + cch]);
                g_h1[ro + cch] = __float2half(fmaxf(w, 0.f));
            }
        } else {
            float dot = 0.f;
            #pragma unroll
            for (int j = 0; j < 8; ++j) {
                int cch = lane + j*32;
                float w = fmaf((v[j] - mu)*rs, par[256 + cch], par[512 + cch]);
                dot = fmaf(fmaxf(w, 0.f), par[768 + cch], dot);
            }
            #pragma unroll
            for (int o = 16; o > 0; o >>= 1)
                dot += __shfl_xor_sync(0xffffffffu, dot, o);
            if (lane == 0)
                dur_out[b*TT + t0 + row] = fmaxf(dot + lin_b[0], 0.f);
        }
    }
}

// ---------------- gather (R11-exact) ----------------
__device__ __forceinline__ void st_cs(float4* p, float4 v) {
    asm volatile("st.global.cs.v4.f32 [%0], {%1,%2,%3,%4};"
                 :: "l"(p), "f"(v.x), "f"(v.y), "f"(v.z), "f"(v.w) : "memory");
}
#define NROWS  (BB*MEL)
#define HROWS  (NROWS/2)
__global__ __launch_bounds__(256)
void gather_k(const float* __restrict__ x, float* __restrict__ out) {
    const long long u  = (long long)blockIdx.x * blockDim.x + threadIdx.x;
    const long long NU = (long long)HROWS * 32;
    if (u >= NU) return;
    const int c8 = (int)(u & 31);
    const long long rowa = u >> 5;
    const long long rowb = rowa + HROWS;
    const int ba = (int)(rowa / MEL);
    const int bb = (int)(rowb / MEL);
    const int ia = __ldg(&g_idx[rowa]);
    const int ib = __ldg(&g_idx[rowb]);
    float4 a0 = make_float4(0.f,0.f,0.f,0.f), a1 = a0, b0 = a0, b1 = a0;
    if (ia >= 0) {
        const float4* s = reinterpret_cast<const float4*>(x) + ((long long)ba*TT + ia)*(DD/4) + c8*2;
        a0 = __ldg(s); a1 = __ldg(s + 1);
    }
    if (ib >= 0) {
        const float4* s = reinterpret_cast<const float4*>(x) + ((long long)bb*TT + ib)*(DD/4) + c8*2;
        b0 = __ldg(s); b1 = __ldg(s + 1);
    }
    float4* da = reinterpret_cast<float4*>(out) + rowa*(DD/4) + c8*2;
    float4* db = reinterpret_cast<float4*>(out) + rowb*(DD/4) + c8*2;
    st_cs(da, a0); st_cs(da + 1, a1);
    st_cs(db, b0); st_cs(db + 1, b1);
}

// ---------------- launch: priority-arbitrated fork/join ----------------
extern "C" void kernel_launch(void* const* d_in, const int* in_sizes, int n_in,
                              void* d_out, int out_size) {
    int base = 2;
    if (n_in >= 13 && in_sizes[2] == 1) base = 3;

    const float* x      = (const float*)d_in[0];
    const int*   target = (const int*)  d_in[1];
    const float* c1w = (const float*)d_in[base + 0];
    const float* c1b = (const float*)d_in[base + 1];
    const float* l1g = (const float*)d_in[base + 2];
    const float* l1b = (const float*)d_in[base + 3];
    const float* c2w = (const float*)d_in[base + 4];
    const float* c2b = (const float*)d_in[base + 5];
    const float* l2g = (const float*)d_in[base + 6];
    const float* l2b = (const float*)d_in[base + 7];
    const float* lw  = (const float*)d_in[base + 8];
    const float* lb  = (const float*)d_in[base + 9];

    float* out = (float*)d_out;
    float* dur = out + (size_t)BB * MEL * DD;

    cudaFuncSetAttribute(conv_wmma<0>, cudaFuncAttributeMaxDynamicSharedMemorySize, SMEM_BYTES);
    cudaFuncSetAttribute(conv_wmma<1>, cudaFuncAttributeMaxDynamicSharedMemorySize, SMEM_BYTES);
    cudaFuncSetAttribute(prep_all,     cudaFuncAttributeMaxDynamicSharedMemorySize, PREP_SMEM);

    const long long NU = (long long)HROWS * 32;
    const int gatherBlocks = (int)((NU + 255)/256);

    int prLo = 0, prHi = 0;
    cudaDeviceGetStreamPriorityRange(&prLo, &prHi);   // prHi = numerically lowest = highest prio

    cudaStream_t sC = nullptr, sG = nullptr;          // conv (high), gather (low)
    cudaEvent_t eP = nullptr, eC = nullptr, eG = nullptr;
    bool forked = (cudaStreamCreateWithPriority(&sC, cudaStreamNonBlocking, prHi) == cudaSuccess)
               && (cudaStreamCreateWithPriority(&sG, cudaStreamNonBlocking, prLo) == cudaSuccess)
               && (cudaEventCreateWithFlags(&eP, cudaEventDisableTiming) == cudaSuccess)
               && (cudaEventCreateWithFlags(&eC, cudaEventDisableTiming) == cudaSuccess)
               && (cudaEventCreateWithFlags(&eG, cudaEventDisableTiming) == cudaSuccess);

    if (forked) {
        // shared prefix (w + x + cum) on origin stream
        prep_all<<<48 + NXBLK, 512, PREP_SMEM>>>(x, c1w, c2w, target);
        cudaEventRecord(eP, 0);

        // convs on HIGH priority: grab SMs as soon as prep drains
        cudaStreamWaitEvent(sC, eP, 0);
        conv_wmma<0><<<BB*NTILES, TPB, SMEM_BYTES, sC>>>(c1b, l1g, l1b, lw, lb, nullptr);
        conv_wmma<1><<<BB*NTILES, TPB, SMEM_BYTES, sC>>>(c2b, l2g, l2b, lw, lb, dur);
        cudaEventRecord(eC, sC);

        // gather on LOW priority: fills bubbles and the tail
        cudaStreamWaitEvent(sG, eP, 0);
        gather_k<<<gatherBlocks, 256, 0, sG>>>(x, out);
        cudaEventRecord(eG, sG);

        cudaStreamWaitEvent(0, eC, 0);
        cudaStreamWaitEvent(0, eG, 0);

        cudaEventDestroy(eP);
        cudaEventDestroy(eC);
        cudaEventDestroy(eG);
        cudaStreamDestroy(sC);
        cudaStreamDestroy(sG);
    } else {
        if (sC) cudaStreamDestroy(sC);
        if (sG) cudaStreamDestroy(sG);
        if (eP) cudaEventDestroy(eP);
        if (eC) cudaEventDestroy(eC);
        if (eG) cudaEventDestroy(eG);

        prep_all<<<48 + NXBLK, 512, PREP_SMEM>>>(x, c1w, c2w, target);
        gather_k<<<gatherBlocks, 256>>>(x, out);
        conv_wmma<0><<<BB*NTILES, TPB, SMEM_BYTES>>>(c1b, l1g, l1b, lw, lb, nullptr);
        conv_wmma<1><<<BB*NTILES, TPB, SMEM_BYTES>>>(c2b, l2g, l2b, lw, lb, dur);
    }
}